// round 1
// baseline (speedup 1.0000x reference)
#include <cuda_runtime.h>

#define C_GRP 11
#define C_MLP 32
#define NPAIR 66              // upper triangle of 11x11
#define NSTAT 77              // 66 + 11
#define GRID_A 592
#define BLK_A  256
#define PSIZE  0.075f
#define XMIN  -54.0f
#define YMIN  -54.0f
#define CZ    -1.0f           // 0.5*(Z_MIN+Z_MAX)
#define BN_EPS 1e-3f

// scratch (no dynamic allocation allowed)
__device__ float g_part[GRID_A * 80];   // per-block partial stats (padded row 80)
__device__ float g_scale[C_MLP];
__device__ float g_bias[C_MLP];

// ---------------------------------------------------------------------------
// Stage 0: zero the output (harness poisons it with 0xAA)
// ---------------------------------------------------------------------------
__global__ void zero_out_kernel(float4* __restrict__ out, int n4) {
    int i = blockIdx.x * blockDim.x + threadIdx.x;
    if (i < n4) out[i] = make_float4(0.f, 0.f, 0.f, 0.f);
}

// ---------------------------------------------------------------------------
// Stage A: accumulate S = sum(g g^T) (upper tri, 66) and s = sum(g) (11)
// ---------------------------------------------------------------------------
__global__ __launch_bounds__(BLK_A)
void stageA_kernel(const float* __restrict__ xyz,
                   const float* __restrict__ ptf,
                   const int*   __restrict__ pil,
                   const int*   __restrict__ psi,
                   int N)
{
    float acc[NPAIR];
    float s[C_GRP];
#pragma unroll
    for (int j = 0; j < NPAIR; j++) acc[j] = 0.f;
#pragma unroll
    for (int j = 0; j < C_GRP; j++) s[j] = 0.f;

    const int stride = GRID_A * BLK_A;
    for (int i = blockIdx.x * BLK_A + threadIdx.x; i < N; i += stride) {
        int p  = psi[i];
        int py = pil[3 * p + 1];
        int px = pil[3 * p + 2];
        float cx = ((float)px + 0.5f) * PSIZE + XMIN;
        float cy = ((float)py + 0.5f) * PSIZE + YMIN;
        float x = xyz[3 * i + 0];
        float y = xyz[3 * i + 1];
        float z = xyz[3 * i + 2];
        float g[C_GRP];
        g[0] = x - cx; g[1] = y - cy; g[2] = z - CZ;
        g[3] = x;      g[4] = y;      g[5] = z;
#pragma unroll
        for (int k = 0; k < 5; k++) g[6 + k] = ptf[5 * i + k];

        int j = 0;
#pragma unroll
        for (int a = 0; a < C_GRP; a++) {
            s[a] += g[a];
#pragma unroll
            for (int b = a; b < C_GRP; b++) {
                acc[j] = fmaf(g[a], g[b], acc[j]);
                j++;
            }
        }
    }

    // warp-level reduction of 77 values
#pragma unroll
    for (int j = 0; j < NPAIR; j++) {
        float v = acc[j];
        v += __shfl_xor_sync(0xffffffffu, v, 16);
        v += __shfl_xor_sync(0xffffffffu, v, 8);
        v += __shfl_xor_sync(0xffffffffu, v, 4);
        v += __shfl_xor_sync(0xffffffffu, v, 2);
        v += __shfl_xor_sync(0xffffffffu, v, 1);
        acc[j] = v;
    }
#pragma unroll
    for (int j = 0; j < C_GRP; j++) {
        float v = s[j];
        v += __shfl_xor_sync(0xffffffffu, v, 16);
        v += __shfl_xor_sync(0xffffffffu, v, 8);
        v += __shfl_xor_sync(0xffffffffu, v, 4);
        v += __shfl_xor_sync(0xffffffffu, v, 2);
        v += __shfl_xor_sync(0xffffffffu, v, 1);
        s[j] = v;
    }

    __shared__ float sm[BLK_A / 32][NSTAT];
    int lane = threadIdx.x & 31;
    int wid  = threadIdx.x >> 5;
    if (lane == 0) {
#pragma unroll
        for (int j = 0; j < NPAIR; j++) sm[wid][j] = acc[j];
#pragma unroll
        for (int j = 0; j < C_GRP; j++) sm[wid][NPAIR + j] = s[j];
    }
    __syncthreads();
    if (threadIdx.x < NSTAT) {
        float t = 0.f;
#pragma unroll
        for (int w = 0; w < BLK_A / 32; w++) t += sm[w][threadIdx.x];
        g_part[blockIdx.x * 80 + threadIdx.x] = t;
    }
}

// ---------------------------------------------------------------------------
// Stage B: reduce partials, compute per-channel BN scale/bias
// scale = gamma * rsqrt(var+eps); bias = beta - mean*scale
// mean_c = (s . w_c)/N ; E[h^2]_c = (w_c^T S w_c)/N ; var = E[h^2]-mean^2
// ---------------------------------------------------------------------------
__global__ void stageB_kernel(const float* __restrict__ W,
                              const float* __restrict__ gamma,
                              const float* __restrict__ beta,
                              int N)
{
    __shared__ float red[NSTAT];
    int t = threadIdx.x;           // 128 threads
    if (t < NSTAT) {
        float a0 = 0.f, a1 = 0.f, a2 = 0.f, a3 = 0.f;
        int b = 0;
        for (; b + 4 <= GRID_A; b += 4) {
            a0 += g_part[(b + 0) * 80 + t];
            a1 += g_part[(b + 1) * 80 + t];
            a2 += g_part[(b + 2) * 80 + t];
            a3 += g_part[(b + 3) * 80 + t];
        }
        for (; b < GRID_A; b++) a0 += g_part[b * 80 + t];
        red[t] = (a0 + a1) + (a2 + a3);
    }
    __syncthreads();
    if (t < C_MLP) {
        float wv[C_GRP];
#pragma unroll
        for (int k = 0; k < C_GRP; k++) wv[k] = W[k * C_MLP + t];
        const float invN = 1.0f / (float)N;

        float mean = 0.f;
#pragma unroll
        for (int k = 0; k < C_GRP; k++) mean = fmaf(wv[k], red[NPAIR + k], mean);
        mean *= invN;

        float ex2 = 0.f;
        int j = 0;
#pragma unroll
        for (int a = 0; a < C_GRP; a++) {
            ex2 = fmaf(wv[a] * wv[a], red[j], ex2);  j++;     // b == a
#pragma unroll
            for (int b2 = a + 1; b2 < C_GRP; b2++) {
                ex2 = fmaf(2.f * wv[a] * wv[b2], red[j], ex2);  j++;
            }
        }
        ex2 *= invN;

        float var = ex2 - mean * mean;
        float sc  = gamma[t] * rsqrtf(var + BN_EPS);
        g_scale[t] = sc;
        g_bias[t]  = fmaf(-mean, sc, beta[t]);
    }
}

// ---------------------------------------------------------------------------
// Stage C: per point: h = g @ W; y = relu(sc*h + bs); atomicMax into pillar.
// y > 0 only (skip zeros — output is 0-initialized). Positive floats order as
// signed ints, so integer atomicMax is exact.
// ---------------------------------------------------------------------------
__global__ __launch_bounds__(256)
void stageC_kernel(const float* __restrict__ xyz,
                   const float* __restrict__ ptf,
                   const float* __restrict__ W,
                   const int*   __restrict__ pil,
                   const int*   __restrict__ psi,
                   float* __restrict__ out,
                   int N)
{
    __shared__ float4 Ws[C_GRP * 8];   // 11 rows x 32 cols
    __shared__ float  sc[C_MLP];
    __shared__ float  bs[C_MLP];
    if (threadIdx.x < C_GRP * 8) {
        Ws[threadIdx.x] = ((const float4*)W)[threadIdx.x];
    }
    if (threadIdx.x >= 128 && threadIdx.x < 160) sc[threadIdx.x - 128] = g_scale[threadIdx.x - 128];
    if (threadIdx.x >= 160 && threadIdx.x < 192) bs[threadIdx.x - 160] = g_bias[threadIdx.x - 160];
    __syncthreads();

    int i = blockIdx.x * blockDim.x + threadIdx.x;
    if (i >= N) return;

    int p  = psi[i];
    int py = pil[3 * p + 1];
    int px = pil[3 * p + 2];
    float cx = ((float)px + 0.5f) * PSIZE + XMIN;
    float cy = ((float)py + 0.5f) * PSIZE + YMIN;
    float x = xyz[3 * i + 0];
    float y = xyz[3 * i + 1];
    float z = xyz[3 * i + 2];
    float g[C_GRP];
    g[0] = x - cx; g[1] = y - cy; g[2] = z - CZ;
    g[3] = x;      g[4] = y;      g[5] = z;
#pragma unroll
    for (int k = 0; k < 5; k++) g[6 + k] = ptf[5 * i + k];

    float h[C_MLP];
#pragma unroll
    for (int c = 0; c < C_MLP; c++) h[c] = 0.f;
#pragma unroll
    for (int k = 0; k < C_GRP; k++) {
        float gk = g[k];
#pragma unroll
        for (int q = 0; q < 8; q++) {
            float4 w = Ws[k * 8 + q];
            h[4 * q + 0] = fmaf(gk, w.x, h[4 * q + 0]);
            h[4 * q + 1] = fmaf(gk, w.y, h[4 * q + 1]);
            h[4 * q + 2] = fmaf(gk, w.z, h[4 * q + 2]);
            h[4 * q + 3] = fmaf(gk, w.w, h[4 * q + 3]);
        }
    }

    int* ob = (int*)(out + (size_t)p * C_MLP);
#pragma unroll
    for (int c = 0; c < C_MLP; c++) {
        float yv = fmaf(sc[c], h[c], bs[c]);
        if (yv > 0.f) atomicMax(ob + c, __float_as_int(yv));
    }
}

// ---------------------------------------------------------------------------
extern "C" void kernel_launch(void* const* d_in, const int* in_sizes, int n_in,
                              void* d_out, int out_size)
{
    const float* xyz   = (const float*)d_in[0];   // (N,3)
    const float* ptf   = (const float*)d_in[1];   // (N,5)
    const float* W1    = (const float*)d_in[2];   // (11,32)
    const float* gamma = (const float*)d_in[3];   // (32)
    const float* beta  = (const float*)d_in[4];   // (32)
    const int*   pil   = (const int*)d_in[5];     // (M,3)
    const int*   psi   = (const int*)d_in[6];     // (N)
    int N = in_sizes[6];
    float* out = (float*)d_out;                   // (M,32)

    int n4 = out_size / 4;
    zero_out_kernel<<<(n4 + 255) / 256, 256>>>((float4*)out, n4);
    stageA_kernel<<<GRID_A, BLK_A>>>(xyz, ptf, pil, psi, N);
    stageB_kernel<<<1, 128>>>(W1, gamma, beta, N);
    stageC_kernel<<<(N + 255) / 256, 256>>>(xyz, ptf, W1, pil, psi, out, N);
}